// round 2
// baseline (speedup 1.0000x reference)
#include <cuda_runtime.h>
#include <cuda_fp16.h>
#include <math.h>
#include <stdint.h>

#define N_NODES 8192
#define D 256
#define NG 8
#define ELLW 768   // max row degree bound; binomial(8192,0.05) max ~ 490

// ---------------- device scratch (no allocations allowed) ----------------
__device__ unsigned short g_cols[(size_t)N_NODES * ELLW];
__device__ int            g_deg[N_NODES];
__device__ float          g_X1[(size_t)N_NODES * D];
__device__ float          g_X2[(size_t)N_NODES * D];
__device__ __half2        g_h2[(size_t)N_NODES * (D / 2)];   // h = X @ W, fp16
__device__ float          g_s1[N_NODES];
__device__ float          g_s2[N_NODES];
__device__ float          g_wa[D];
__device__ float          g_wb[D];
__device__ float          g_Spart[32][D];
__device__ float          g_S[D];
__device__ float          g_mid[(size_t)N_NODES * 64];
__device__ float          g_gpart[(size_t)64 * NG * D];
__device__ int            g_gcntp[64 * NG];
__device__ float          g_gsum[NG * D];
__device__ float          g_gcnt[NG];

// ---------------- helpers ----------------
__device__ __forceinline__ float gelu_exact(float x) {
    return 0.5f * x * (1.0f + erff(x * 0.70710678118654752f));
}

__device__ __forceinline__ float block_sum_128(float v, volatile float* red) {
    int lane = threadIdx.x & 31, w = threadIdx.x >> 5;
#pragma unroll
    for (int o = 16; o > 0; o >>= 1) v += __shfl_down_sync(0xffffffffu, v, o);
    __syncthreads();
    if (lane == 0) red[w] = v;
    __syncthreads();
    return red[0] + red[1] + red[2] + red[3];
}

__device__ __forceinline__ float block_max_128(float v, volatile float* red) {
    int lane = threadIdx.x & 31, w = threadIdx.x >> 5;
#pragma unroll
    for (int o = 16; o > 0; o >>= 1) v = fmaxf(v, __shfl_down_sync(0xffffffffu, v, o));
    __syncthreads();
    if (lane == 0) red[w] = v;
    __syncthreads();
    return fmaxf(fmaxf(red[0], red[1]), fmaxf(red[2], red[3]));
}

// ---------------- 0: dense adj -> ELL (deterministic, sorted cols) ----------------
__global__ void build_ell_kernel(const float* __restrict__ adj) {
    int i = blockIdx.x;
    int tid = threadIdx.x;             // 256
    int lane = tid & 31, w = tid >> 5;
    __shared__ int wcnt[8];
    const float* row = adj + (size_t)i * N_NODES;
    int base = 0;
    for (int c0 = 0; c0 < N_NODES; c0 += 256) {
        int c = c0 + tid;
        bool pred = (row[c] != 0.0f);
        unsigned bal = __ballot_sync(0xffffffffu, pred);
        if (lane == 0) wcnt[w] = __popc(bal);
        __syncthreads();
        int off = 0, tot = 0;
#pragma unroll
        for (int k = 0; k < 8; k++) { int v = wcnt[k]; tot += v; if (k < w) off += v; }
        if (pred) {
            int pos = base + off + __popc(bal & ((1u << lane) - 1u));
            if (pos < ELLW) g_cols[(size_t)i * ELLW + pos] = (unsigned short)c;
        }
        base += tot;
        __syncthreads();
    }
    if (tid == 0) g_deg[i] = (base < ELLW) ? base : ELLW;
}

// ---------------- 1: wa = W @ a_top, wb = W @ a_bot ----------------
__global__ void wavec_kernel(const float* __restrict__ W, const float* __restrict__ a) {
    __shared__ float at[D], ab[D];
    int t = threadIdx.x; // 256
    at[t] = a[t];
    ab[t] = a[D + t];
    __syncthreads();
    float s1 = 0.0f, s2 = 0.0f;
    const float* wr = W + (size_t)t * D;
#pragma unroll 8
    for (int c = 0; c < D; c++) { float w = wr[c]; s1 += w * at[c]; s2 += w * ab[c]; }
    g_wa[t] = s1;
    g_wb[t] = s2;
}

// ---------------- 2: s1 = X @ wa, s2 = X @ wb (fp32 exact logit path) ----------------
__global__ void s12_kernel(const float* __restrict__ X) {
    int w = threadIdx.x >> 5, lane = threadIdx.x & 31;
    int i = blockIdx.x * 8 + w;
    const float* xr = X + (size_t)i * D;
    float a1 = 0.0f, a2 = 0.0f;
#pragma unroll
    for (int jj = 0; jj < 8; jj++) {
        int j = jj * 32 + lane;
        float x = xr[j];
        a1 += x * g_wa[j];
        a2 += x * g_wb[j];
    }
#pragma unroll
    for (int o = 16; o > 0; o >>= 1) {
        a1 += __shfl_down_sync(0xffffffffu, a1, o);
        a2 += __shfl_down_sync(0xffffffffu, a2, o);
    }
    if (lane == 0) { g_s1[i] = a1; g_s2[i] = a2; }
}

// ---------------- 3: fp32 GEMM C = act(A@B + bias). ACT 1=gelu+bias. OUTH 1=half out ----------------
template <int ACT, int OUTH>
__global__ void gemm_kernel(const float* __restrict__ A, const float* __restrict__ B,
                            const float* __restrict__ bias, void* __restrict__ C,
                            int M, int N, int K) {
    const int BM = 64, BN = 64, BK = 16;
    __shared__ __align__(16) float As[BK][BM];
    __shared__ __align__(16) float Bs[BK][BN];
    int tid = threadIdx.x;  // 256
    int m0 = blockIdx.y * BM, n0 = blockIdx.x * BN;
    int tx = tid & 15, ty = tid >> 4;
    float acc[4][4];
#pragma unroll
    for (int i = 0; i < 4; i++)
#pragma unroll
        for (int j = 0; j < 4; j++) acc[i][j] = 0.0f;

    for (int k0 = 0; k0 < K; k0 += BK) {
        {
            int r = tid >> 2, c = (tid & 3) * 4;
            float4 v = *reinterpret_cast<const float4*>(&A[(size_t)(m0 + r) * K + k0 + c]);
            As[c + 0][r] = v.x; As[c + 1][r] = v.y; As[c + 2][r] = v.z; As[c + 3][r] = v.w;
        }
        {
            int r = tid >> 4, c = (tid & 15) * 4;
            float4 v = *reinterpret_cast<const float4*>(&B[(size_t)(k0 + r) * N + n0 + c]);
            *reinterpret_cast<float4*>(&Bs[r][c]) = v;
        }
        __syncthreads();
#pragma unroll
        for (int kk = 0; kk < BK; kk++) {
            float4 av = *reinterpret_cast<const float4*>(&As[kk][ty * 4]);
            float4 bv = *reinterpret_cast<const float4*>(&Bs[kk][tx * 4]);
            float a4[4] = {av.x, av.y, av.z, av.w};
            float b4[4] = {bv.x, bv.y, bv.z, bv.w};
#pragma unroll
            for (int i = 0; i < 4; i++)
#pragma unroll
                for (int j = 0; j < 4; j++) acc[i][j] += a4[i] * b4[j];
        }
        __syncthreads();
    }
#pragma unroll
    for (int i = 0; i < 4; i++)
#pragma unroll
        for (int j = 0; j < 4; j++) {
            int r = m0 + ty * 4 + i, c = n0 + tx * 4 + j;
            float v = acc[i][j];
            if (ACT == 1) { v += bias[c]; v = gelu_exact(v); }
            if (OUTH) ((__half*)C)[(size_t)r * N + c] = __float2half(v);
            else      ((float*)C)[(size_t)r * N + c] = v;
        }
}

// ---------------- 4: column sum of h ----------------
__global__ void colsum_part_kernel() {
    int d = threadIdx.x, b = blockIdx.x;  // 32 blocks
    const __half* h = reinterpret_cast<const __half*>(g_h2);
    float s = 0.0f;
    int r0 = b * (N_NODES / 32);
    for (int r = r0; r < r0 + (N_NODES / 32); r++) s += __half2float(h[(size_t)r * D + d]);
    g_Spart[b][d] = s;
}
__global__ void colsum_red_kernel() {
    int d = threadIdx.x;
    float s = 0.0f;
#pragma unroll
    for (int b = 0; b < 32; b++) s += g_Spart[b][d];
    g_S[d] = s;
}

// ---------------- 5: GAT row: softmax decomposition + ELL SpMM + ELU + LN + residual ----------------
__global__ __launch_bounds__(128) void gat_row_kernel(const float* __restrict__ Xin,
                                                      const float* __restrict__ lng,
                                                      const float* __restrict__ lnb,
                                                      float* __restrict__ Xout,
                                                      int residual) {
    const int i = blockIdx.x;
    const int t = threadIdx.x;   // 128; thread t owns features (2t, 2t+1)
    __shared__ int   cols_sm[ELLW];
    __shared__ float s2_sm[ELLW];
    __shared__ float c_sm[ELLW];
    __shared__ float red[4];

    const int deg = g_deg[i];
    const float s1 = g_s1[i];

    for (int k = t; k < deg; k += 128) {
        int j = (int)g_cols[(size_t)i * ELLW + k];
        cols_sm[k] = j;
        s2_sm[k] = g_s2[j];
    }
    __syncthreads();

    // exact row max: m = max(0, lrelu(s1 + max_j s2_j))
    float tmax = -1e30f;
    for (int k = t; k < deg; k += 128) tmax = fmaxf(tmax, s2_sm[k]);
    tmax = block_max_128(tmax, red);
    float m;
    {
        float z = s1 + tmax;
        float lr = (z > 0.0f) ? z : 0.2f * z;
        m = fmaxf(lr, 0.0f);
        if (deg == 0) m = 0.0f;
    }
    const float q = __expf(-m);  // exp(e-m) at every non-edge (e=0)

    float zp = 0.0f;
    for (int k = t; k < deg; k += 128) {
        float z = s1 + s2_sm[k];
        float lr = (z > 0.0f) ? z : 0.2f * z;
        float p = __expf(lr - m);
        zp += p;
        c_sm[k] = p - q;
    }
    __syncthreads();
    float Z = block_sum_128(zp, red) + (float)(N_NODES - deg) * q;

    // SpMM: acc = sum_edges (p-q) * h[j] + q*S
    float accx = 0.0f, accy = 0.0f;
#pragma unroll 4
    for (int k = 0; k < deg; k++) {
        float c = c_sm[k];
        int j = cols_sm[k];
        float2 f = __half22float2(g_h2[(size_t)j * 128 + t]);
        accx += c * f.x;
        accy += c * f.y;
    }
    accx += q * g_S[2 * t];
    accy += q * g_S[2 * t + 1];

    float rx = accx / Z, ry = accy / Z;
    float vx = (rx > 0.0f) ? rx : expm1f(rx);
    float vy = (ry > 0.0f) ? ry : expm1f(ry);

    // LayerNorm over D=256 (biased var, eps 1e-5) + optional residual
    float sum = block_sum_128(vx + vy, red);
    float mean = sum * (1.0f / 256.0f);
    float dx = vx - mean, dy = vy - mean;
    float sq = block_sum_128(dx * dx + dy * dy, red);
    float rstd = rsqrtf(sq * (1.0f / 256.0f) + 1e-5f);
    float yx = dx * rstd * lng[2 * t] + lnb[2 * t];
    float yy = dy * rstd * lng[2 * t + 1] + lnb[2 * t + 1];
    if (residual) {
        float2 xr = *reinterpret_cast<const float2*>(&Xin[(size_t)i * D + 2 * t]);
        yx += xr.x;
        yy += xr.y;
    }
    float2 o; o.x = yx; o.y = yy;
    *reinterpret_cast<float2*>(&Xout[(size_t)i * D + 2 * t]) = o;
}

// ---------------- 6: node logits (8192x64)@(64x5)+b ----------------
__global__ void node_logits_kernel(const float* __restrict__ mid, const float* __restrict__ w2,
                                   const float* __restrict__ b2, float* __restrict__ out) {
    int i = blockIdx.x, t = threadIdx.x;  // 64
    __shared__ float sm[64];
    sm[t] = mid[(size_t)i * 64 + t];
    __syncthreads();
    if (t < 5) {
        float s = b2[t];
#pragma unroll 8
        for (int k = 0; k < 64; k++) s += sm[k] * w2[k * 5 + t];
        out[(size_t)i * 5 + t] = s;
    }
}

// ---------------- 7: deterministic segment pooling ----------------
__global__ void pool_part_kernel(const float* __restrict__ h3, const int* __restrict__ mask) {
    __shared__ float sacc[NG * D];
    int d = threadIdx.x;  // 256
    int b = blockIdx.x;   // 64 blocks x 128 rows
#pragma unroll
    for (int g = 0; g < NG; g++) sacc[g * D + d] = 0.0f;
    __syncthreads();
    int r0 = b * 128, lc = 0;
    for (int r = r0; r < r0 + 128; r++) {
        int g = mask[r];
        sacc[g * D + d] += h3[(size_t)r * D + d];
        if (d < NG && g == d) lc++;
    }
    __syncthreads();
#pragma unroll
    for (int g = 0; g < NG; g++)
        g_gpart[((size_t)b * NG + g) * D + d] = sacc[g * D + d];
    if (d < NG) g_gcntp[b * NG + d] = lc;
}
__global__ void pool_red_kernel() {
    int g = blockIdx.x, d = threadIdx.x;  // 8 x 256
    float s = 0.0f;
    for (int b = 0; b < 64; b++) s += g_gpart[((size_t)b * NG + g) * D + d];
    g_gsum[g * D + d] = s;
    if (d == 0) {
        int c = 0;
        for (int b = 0; b < 64; b++) c += g_gcntp[b * NG + g];
        g_gcnt[g] = (float)c;
    }
}

// ---------------- 8: graph heads ----------------
__global__ void graph_head_kernel(const float* __restrict__ gc_w1, const float* __restrict__ gc_b1,
                                  const float* __restrict__ gc_w2, const float* __restrict__ gc_b2,
                                  const float* __restrict__ rs_w1, const float* __restrict__ rs_b1,
                                  const float* __restrict__ rs_w2, const float* __restrict__ rs_b2,
                                  float* __restrict__ graph_logits, float* __restrict__ risk) {
    __shared__ float ge[D];
    __shared__ float hid[64];
    __shared__ float hid2[32];
    int d = threadIdx.x;  // 256
    for (int g = 0; g < NG; g++) {
        float cnt = fmaxf(g_gcnt[g], 1.0f);
        ge[d] = g_gsum[g * D + d] / cnt;
        __syncthreads();
        if (d < 64) {
            float s = gc_b1[d];
            for (int k = 0; k < D; k++) s += ge[k] * gc_w1[k * 64 + d];
            hid[d] = gelu_exact(s);
        } else if (d < 96) {
            int t = d - 64;
            float s = rs_b1[t];
            for (int k = 0; k < D; k++) s += ge[k] * rs_w1[k * 32 + t];
            hid2[t] = gelu_exact(s);
        }
        __syncthreads();
        if (d < 3) {
            float s = gc_b2[d];
            for (int k = 0; k < 64; k++) s += hid[k] * gc_w2[k * 3 + d];
            graph_logits[g * 3 + d] = s;
        }
        if (d == 3) {
            float s = rs_b2[0];
            for (int k = 0; k < 32; k++) s += hid2[k] * rs_w2[k];
            risk[g] = 1.0f / (1.0f + expf(-s));
        }
        __syncthreads();
    }
}

// ---------------- launch ----------------
extern "C" void kernel_launch(void* const* d_in, const int* in_sizes, int n_in,
                              void* d_out, int out_size) {
    const float* x    = (const float*)d_in[0];
    const float* adj  = (const float*)d_in[1];
    const int*   mask = (const int*)d_in[2];
    const float* W[3]   = {(const float*)d_in[3], (const float*)d_in[5], (const float*)d_in[7]};
    const float* a[3]   = {(const float*)d_in[4], (const float*)d_in[6], (const float*)d_in[8]};
    const float* lng[3] = {(const float*)d_in[9],  (const float*)d_in[11], (const float*)d_in[13]};
    const float* lnb[3] = {(const float*)d_in[10], (const float*)d_in[12], (const float*)d_in[14]};
    const float* nc_w1 = (const float*)d_in[15];
    const float* nc_b1 = (const float*)d_in[16];
    const float* nc_w2 = (const float*)d_in[17];
    const float* nc_b2 = (const float*)d_in[18];
    const float* gc_w1 = (const float*)d_in[19];
    const float* gc_b1 = (const float*)d_in[20];
    const float* gc_w2 = (const float*)d_in[21];
    const float* gc_b2 = (const float*)d_in[22];
    const float* rs_w1 = (const float*)d_in[23];
    const float* rs_b1 = (const float*)d_in[24];
    const float* rs_w2 = (const float*)d_in[25];
    const float* rs_b2 = (const float*)d_in[26];

    float* out = (float*)d_out;
    float* out_node  = out;                 // 8192*5
    float* out_graph = out + 40960;         // 8*3
    float* out_risk  = out + 40984;         // 8
    float* out_h3    = out + 40992;         // 8192*256

    // resolve device-global scratch addresses
    float *pX1, *pX2; void* ph;
    cudaGetSymbolAddress((void**)&pX1, g_X1);
    cudaGetSymbolAddress((void**)&pX2, g_X2);
    cudaGetSymbolAddress(&ph, g_h2);
    float* pmid; cudaGetSymbolAddress((void**)&pmid, g_mid);

    build_ell_kernel<<<N_NODES, 256>>>(adj);

    const float* Xprev = x;
    float* Xouts[3] = {pX1, pX2, out_h3};
    for (int L = 0; L < 3; L++) {
        wavec_kernel<<<1, 256>>>(W[L], a[L]);
        s12_kernel<<<N_NODES / 8, 256>>>(Xprev);
        gemm_kernel<0, 1><<<dim3(D / 64, N_NODES / 64), 256>>>(Xprev, W[L], nullptr, ph,
                                                               N_NODES, D, D);
        colsum_part_kernel<<<32, 256>>>();
        colsum_red_kernel<<<1, 256>>>();
        gat_row_kernel<<<N_NODES, 128>>>(Xprev, lng[L], lnb[L], Xouts[L], L > 0 ? 1 : 0);
        Xprev = Xouts[L];
    }

    // node head: mid = gelu(h3 @ nc_w1 + b1); logits = mid @ nc_w2 + b2
    gemm_kernel<1, 0><<<dim3(1, N_NODES / 64), 256>>>(out_h3, nc_w1, nc_b1, pmid,
                                                      N_NODES, 64, D);
    node_logits_kernel<<<N_NODES, 64>>>(pmid, nc_w2, nc_b2, out_node);

    // graph heads
    pool_part_kernel<<<64, 256>>>(out_h3, mask);
    pool_red_kernel<<<NG, 256>>>();
    graph_head_kernel<<<1, 256>>>(gc_w1, gc_b1, gc_w2, gc_b2,
                                  rs_w1, rs_b1, rs_w2, rs_b2,
                                  out_graph, out_risk);
}

// round 4
// speedup vs baseline: 1.0123x; 1.0123x over previous
#include <cuda_runtime.h>
#include <cuda_fp16.h>
#include <math.h>
#include <stdint.h>

#define N_NODES 8192
#define D 256
#define NG 8
#define ELLW 768   // max row degree bound; binomial(8192,0.05) max ~ 490

// ---------------- device scratch (no allocations allowed) ----------------
__device__ unsigned short g_cols[(size_t)N_NODES * ELLW];
__device__ int            g_deg[N_NODES];
__device__ float          g_X1[(size_t)N_NODES * D];
__device__ float          g_X2[(size_t)N_NODES * D];
__device__ __half2        g_h2[(size_t)N_NODES * (D / 2)];   // h = X @ W, fp16
__device__ float          g_s1[N_NODES];
__device__ float          g_s2[N_NODES];
__device__ float          g_wa[D];
__device__ float          g_wb[D];
__device__ float          g_Spart[32][D];
__device__ float          g_S[D];
__device__ float          g_mid[(size_t)N_NODES * 64];
__device__ float          g_gpart[(size_t)64 * NG * D];
__device__ int            g_gcntp[64 * NG];
__device__ float          g_gsum[NG * D];
__device__ float          g_gcnt[NG];

// ---------------- helpers ----------------
__device__ __forceinline__ float gelu_exact(float x) {
    return 0.5f * x * (1.0f + erff(x * 0.70710678118654752f));
}

__device__ __forceinline__ float block_sum_128(float v, volatile float* red) {
    int lane = threadIdx.x & 31, w = threadIdx.x >> 5;
#pragma unroll
    for (int o = 16; o > 0; o >>= 1) v += __shfl_down_sync(0xffffffffu, v, o);
    __syncthreads();
    if (lane == 0) red[w] = v;
    __syncthreads();
    return red[0] + red[1] + red[2] + red[3];
}

__device__ __forceinline__ float block_max_128(float v, volatile float* red) {
    int lane = threadIdx.x & 31, w = threadIdx.x >> 5;
#pragma unroll
    for (int o = 16; o > 0; o >>= 1) v = fmaxf(v, __shfl_down_sync(0xffffffffu, v, o));
    __syncthreads();
    if (lane == 0) red[w] = v;
    __syncthreads();
    return fmaxf(fmaxf(red[0], red[1]), fmaxf(red[2], red[3]));
}

// ---------------- 0: dense adj -> ELL (deterministic, sorted cols) ----------------
__global__ void build_ell_kernel(const float* __restrict__ adj) {
    int i = blockIdx.x;
    int tid = threadIdx.x;             // 256
    int lane = tid & 31, w = tid >> 5;
    __shared__ int wcnt[8];
    const float* row = adj + (size_t)i * N_NODES;
    int base = 0;
    for (int c0 = 0; c0 < N_NODES; c0 += 256) {
        int c = c0 + tid;
        bool pred = (row[c] != 0.0f);
        unsigned bal = __ballot_sync(0xffffffffu, pred);
        if (lane == 0) wcnt[w] = __popc(bal);
        __syncthreads();
        int off = 0, tot = 0;
#pragma unroll
        for (int k = 0; k < 8; k++) { int v = wcnt[k]; tot += v; if (k < w) off += v; }
        if (pred) {
            int pos = base + off + __popc(bal & ((1u << lane) - 1u));
            if (pos < ELLW) g_cols[(size_t)i * ELLW + pos] = (unsigned short)c;
        }
        base += tot;
        __syncthreads();
    }
    if (tid == 0) g_deg[i] = (base < ELLW) ? base : ELLW;
}

// ---------------- 1: wa = W @ a_top, wb = W @ a_bot ----------------
__global__ void wavec_kernel(const float* __restrict__ W, const float* __restrict__ a) {
    __shared__ float at[D], ab[D];
    int t = threadIdx.x; // 256
    at[t] = a[t];
    ab[t] = a[D + t];
    __syncthreads();
    float s1 = 0.0f, s2 = 0.0f;
    const float* wr = W + (size_t)t * D;
#pragma unroll 8
    for (int c = 0; c < D; c++) { float w = wr[c]; s1 += w * at[c]; s2 += w * ab[c]; }
    g_wa[t] = s1;
    g_wb[t] = s2;
}

// ---------------- 2: s1 = X @ wa, s2 = X @ wb (fp32 exact logit path) ----------------
__global__ void s12_kernel(const float* __restrict__ X) {
    int w = threadIdx.x >> 5, lane = threadIdx.x & 31;
    int i = blockIdx.x * 8 + w;
    const float* xr = X + (size_t)i * D;
    float a1 = 0.0f, a2 = 0.0f;
#pragma unroll
    for (int jj = 0; jj < 8; jj++) {
        int j = jj * 32 + lane;
        float x = xr[j];
        a1 += x * g_wa[j];
        a2 += x * g_wb[j];
    }
#pragma unroll
    for (int o = 16; o > 0; o >>= 1) {
        a1 += __shfl_down_sync(0xffffffffu, a1, o);
        a2 += __shfl_down_sync(0xffffffffu, a2, o);
    }
    if (lane == 0) { g_s1[i] = a1; g_s2[i] = a2; }
}

// ---------------- 3: fp32 GEMM C = act(A@B + bias). BM=128,BN=64, 8x4 microtile ----------------
template <int ACT, int OUTH>
__global__ __launch_bounds__(256) void gemm_kernel(const float* __restrict__ A,
                                                   const float* __restrict__ B,
                                                   const float* __restrict__ bias,
                                                   void* __restrict__ C,
                                                   int M, int N, int K) {
    const int BM = 128, BN = 64, BK = 16;
    __shared__ __align__(16) float As[BK][BM];
    __shared__ __align__(16) float Bs[BK][BN];
    int tid = threadIdx.x;  // 256
    int m0 = blockIdx.y * BM, n0 = blockIdx.x * BN;
    int tx = tid & 15, ty = tid >> 4;   // ty 0..15 (rows x8), tx 0..15 (cols x4)
    float acc[8][4];
#pragma unroll
    for (int i = 0; i < 8; i++)
#pragma unroll
        for (int j = 0; j < 4; j++) acc[i][j] = 0.0f;

    int ar = tid >> 1;               // 0..127
    int ac = (tid & 1) * 8;          // 0 or 8
    int br = tid >> 4;               // 0..15
    int bc = (tid & 15) * 4;         // 0..60

    for (int k0 = 0; k0 < K; k0 += BK) {
        {
            const float* ap = &A[(size_t)(m0 + ar) * K + k0 + ac];
            float4 v0 = *reinterpret_cast<const float4*>(ap);
            float4 v1 = *reinterpret_cast<const float4*>(ap + 4);
            As[ac + 0][ar] = v0.x; As[ac + 1][ar] = v0.y;
            As[ac + 2][ar] = v0.z; As[ac + 3][ar] = v0.w;
            As[ac + 4][ar] = v1.x; As[ac + 5][ar] = v1.y;
            As[ac + 6][ar] = v1.z; As[ac + 7][ar] = v1.w;
        }
        {
            float4 v = *reinterpret_cast<const float4*>(&B[(size_t)(k0 + br) * N + n0 + bc]);
            *reinterpret_cast<float4*>(&Bs[br][bc]) = v;
        }
        __syncthreads();
#pragma unroll
        for (int kk = 0; kk < BK; kk++) {
            float4 a0 = *reinterpret_cast<const float4*>(&As[kk][ty * 8]);
            float4 a1 = *reinterpret_cast<const float4*>(&As[kk][ty * 8 + 4]);
            float4 bv = *reinterpret_cast<const float4*>(&Bs[kk][tx * 4]);
            float a8[8] = {a0.x, a0.y, a0.z, a0.w, a1.x, a1.y, a1.z, a1.w};
            float b4[4] = {bv.x, bv.y, bv.z, bv.w};
#pragma unroll
            for (int i = 0; i < 8; i++)
#pragma unroll
                for (int j = 0; j < 4; j++) acc[i][j] += a8[i] * b4[j];
        }
        __syncthreads();
    }
#pragma unroll
    for (int i = 0; i < 8; i++)
#pragma unroll
        for (int j = 0; j < 4; j++) {
            int r = m0 + ty * 8 + i, c = n0 + tx * 4 + j;
            float v = acc[i][j];
            if (ACT == 1) { v += bias[c]; v = gelu_exact(v); }
            if (OUTH) ((__half*)C)[(size_t)r * N + c] = __float2half(v);
            else      ((float*)C)[(size_t)r * N + c] = v;
        }
}

// ---------------- 4: column sum of h ----------------
__global__ void colsum_part_kernel() {
    int d = threadIdx.x, b = blockIdx.x;  // 32 blocks
    const __half* h = reinterpret_cast<const __half*>(g_h2);
    float s = 0.0f;
    int r0 = b * (N_NODES / 32);
    for (int r = r0; r < r0 + (N_NODES / 32); r++) s += __half2float(h[(size_t)r * D + d]);
    g_Spart[b][d] = s;
}
__global__ void colsum_red_kernel() {
    int d = threadIdx.x;
    float s = 0.0f;
#pragma unroll
    for (int b = 0; b < 32; b++) s += g_Spart[b][d];
    g_S[d] = s;
}

// ---------------- 5: GAT row: softmax decomposition + ELL SpMM + ELU + LN + residual ----------------
__global__ __launch_bounds__(128) void gat_row_kernel(const float* __restrict__ Xin,
                                                      const float* __restrict__ lng,
                                                      const float* __restrict__ lnb,
                                                      float* __restrict__ Xout,
                                                      int residual) {
    const int i = blockIdx.x;
    const int t = threadIdx.x;   // 128; thread t owns features (2t, 2t+1)
    __shared__ __align__(8) float2 csm[ELLW];  // .x: s2 then coef, .y: col bits
    __shared__ float red[4];

    const int deg = g_deg[i];
    const float s1 = g_s1[i];
    const unsigned short* __restrict__ crow = g_cols + (size_t)i * ELLW;

    for (int k = t; k < deg; k += 128) {
        int j = (int)crow[k];
        csm[k] = make_float2(g_s2[j], __int_as_float(j));
    }
    __syncthreads();

    // exact row max: m = max(0, lrelu(s1 + max_j s2_j))
    float tmax = -1e30f;
    for (int k = t; k < deg; k += 128) tmax = fmaxf(tmax, csm[k].x);
    tmax = block_max_128(tmax, red);
    float m;
    {
        float z = s1 + tmax;
        float lr = (z > 0.0f) ? z : 0.2f * z;
        m = fmaxf(lr, 0.0f);
        if (deg == 0) m = 0.0f;
    }
    const float q = __expf(-m);  // exp(e-m) at every non-edge (e=0)

    float zp = 0.0f;
    for (int k = t; k < deg; k += 128) {
        float z = s1 + csm[k].x;
        float lr = (z > 0.0f) ? z : 0.2f * z;
        float p = __expf(lr - m);
        zp += p;
        csm[k].x = p - q;
    }
    float Z = block_sum_128(zp, red) + (float)(N_NODES - deg) * q;  // sync inside publishes csm

    // SpMM: acc = sum_edges (p-q) * h[j] + q*S
    const __half2* __restrict__ hp = g_h2;
    float accx = 0.0f, accy = 0.0f;
#pragma unroll 8
    for (int k = 0; k < deg; k++) {
        float2 e = csm[k];
        int j = __float_as_int(e.y);
        float2 f = __half22float2(__ldg(&hp[(size_t)(j << 7) + t]));
        accx += e.x * f.x;
        accy += e.x * f.y;
    }
    accx += q * g_S[2 * t];
    accy += q * g_S[2 * t + 1];

    float rx = accx / Z, ry = accy / Z;
    float vx = (rx > 0.0f) ? rx : expm1f(rx);
    float vy = (ry > 0.0f) ? ry : expm1f(ry);

    // LayerNorm over D=256 (biased var, eps 1e-5) + optional residual
    float sum = block_sum_128(vx + vy, red);
    float mean = sum * (1.0f / 256.0f);
    float dx = vx - mean, dy = vy - mean;
    float sq = block_sum_128(dx * dx + dy * dy, red);
    float rstd = rsqrtf(sq * (1.0f / 256.0f) + 1e-5f);
    float2 gv = *reinterpret_cast<const float2*>(&lng[2 * t]);
    float2 bv = *reinterpret_cast<const float2*>(&lnb[2 * t]);
    float yx = dx * rstd * gv.x + bv.x;
    float yy = dy * rstd * gv.y + bv.y;
    if (residual) {
        float2 xr = *reinterpret_cast<const float2*>(&Xin[(size_t)i * D + 2 * t]);
        yx += xr.x;
        yy += xr.y;
    }
    float2 o; o.x = yx; o.y = yy;
    *reinterpret_cast<float2*>(&Xout[(size_t)i * D + 2 * t]) = o;
}

// ---------------- 6: node logits (8192x64)@(64x5)+b ----------------
__global__ void node_logits_kernel(const float* __restrict__ mid, const float* __restrict__ w2,
                                   const float* __restrict__ b2, float* __restrict__ out) {
    int i = blockIdx.x, t = threadIdx.x;  // 64
    __shared__ float sm[64];
    sm[t] = mid[(size_t)i * 64 + t];
    __syncthreads();
    if (t < 5) {
        float s = b2[t];
#pragma unroll 8
        for (int k = 0; k < 64; k++) s += sm[k] * w2[k * 5 + t];
        out[(size_t)i * 5 + t] = s;
    }
}

// ---------------- 7: deterministic segment pooling ----------------
__global__ void pool_part_kernel(const float* __restrict__ h3, const int* __restrict__ mask) {
    __shared__ float sacc[NG * D];
    int d = threadIdx.x;  // 256
    int b = blockIdx.x;   // 64 blocks x 128 rows
#pragma unroll
    for (int g = 0; g < NG; g++) sacc[g * D + d] = 0.0f;
    __syncthreads();
    int r0 = b * 128, lc = 0;
    for (int r = r0; r < r0 + 128; r++) {
        int g = mask[r];
        sacc[g * D + d] += h3[(size_t)r * D + d];
        if (d < NG && g == d) lc++;
    }
    __syncthreads();
#pragma unroll
    for (int g = 0; g < NG; g++)
        g_gpart[((size_t)b * NG + g) * D + d] = sacc[g * D + d];
    if (d < NG) g_gcntp[b * NG + d] = lc;
}
__global__ void pool_red_kernel() {
    int g = blockIdx.x, d = threadIdx.x;  // 8 x 256
    float s = 0.0f;
    for (int b = 0; b < 64; b++) s += g_gpart[((size_t)b * NG + g) * D + d];
    g_gsum[g * D + d] = s;
    if (d == 0) {
        int c = 0;
        for (int b = 0; b < 64; b++) c += g_gcntp[b * NG + g];
        g_gcnt[g] = (float)c;
    }
}

// ---------------- 8: graph heads ----------------
__global__ void graph_head_kernel(const float* __restrict__ gc_w1, const float* __restrict__ gc_b1,
                                  const float* __restrict__ gc_w2, const float* __restrict__ gc_b2,
                                  const float* __restrict__ rs_w1, const float* __restrict__ rs_b1,
                                  const float* __restrict__ rs_w2, const float* __restrict__ rs_b2,
                                  float* __restrict__ graph_logits, float* __restrict__ risk) {
    __shared__ float ge[D];
    __shared__ float hid[64];
    __shared__ float hid2[32];
    int d = threadIdx.x;  // 256
    for (int g = 0; g < NG; g++) {
        float cnt = fmaxf(g_gcnt[g], 1.0f);
        ge[d] = g_gsum[g * D + d] / cnt;
        __syncthreads();
        if (d < 64) {
            float s = gc_b1[d];
            for (int k = 0; k < D; k++) s += ge[k] * gc_w1[k * 64 + d];
            hid[d] = gelu_exact(s);
        } else if (d < 96) {
            int t = d - 64;
            float s = rs_b1[t];
            for (int k = 0; k < D; k++) s += ge[k] * rs_w1[k * 32 + t];
            hid2[t] = gelu_exact(s);
        }
        __syncthreads();
        if (d < 3) {
            float s = gc_b2[d];
            for (int k = 0; k < 64; k++) s += hid[k] * gc_w2[k * 3 + d];
            graph_logits[g * 3 + d] = s;
        }
        if (d == 3) {
            float s = rs_b2[0];
            for (int k = 0; k < 32; k++) s += hid2[k] * rs_w2[k];
            risk[g] = 1.0f / (1.0f + expf(-s));
        }
        __syncthreads();
    }
}

// ---------------- launch ----------------
extern "C" void kernel_launch(void* const* d_in, const int* in_sizes, int n_in,
                              void* d_out, int out_size) {
    const float* x    = (const float*)d_in[0];
    const float* adj  = (const float*)d_in[1];
    const int*   mask = (const int*)d_in[2];
    const float* W[3]   = {(const float*)d_in[3], (const float*)d_in[5], (const float*)d_in[7]};
    const float* a[3]   = {(const float*)d_in[4], (const float*)d_in[6], (const float*)d_in[8]};
    const float* lng[3] = {(const float*)d_in[9],  (const float*)d_in[11], (const float*)d_in[13]};
    const float* lnb[3] = {(const float*)d_in[10], (const float*)d_in[12], (const float*)d_in[14]};
    const float* nc_w1 = (const float*)d_in[15];
    const float* nc_b1 = (const float*)d_in[16];
    const float* nc_w2 = (const float*)d_in[17];
    const float* nc_b2 = (const float*)d_in[18];
    const float* gc_w1 = (const float*)d_in[19];
    const float* gc_b1 = (const float*)d_in[20];
    const float* gc_w2 = (const float*)d_in[21];
    const float* gc_b2 = (const float*)d_in[22];
    const float* rs_w1 = (const float*)d_in[23];
    const float* rs_b1 = (const float*)d_in[24];
    const float* rs_w2 = (const float*)d_in[25];
    const float* rs_b2 = (const float*)d_in[26];

    float* out = (float*)d_out;
    float* out_node  = out;                 // 8192*5
    float* out_graph = out + 40960;         // 8*3
    float* out_risk  = out + 40984;         // 8
    float* out_h3    = out + 40992;         // 8192*256

    // resolve device-global scratch addresses
    float *pX1, *pX2; void* ph;
    cudaGetSymbolAddress((void**)&pX1, g_X1);
    cudaGetSymbolAddress((void**)&pX2, g_X2);
    cudaGetSymbolAddress(&ph, g_h2);
    float* pmid; cudaGetSymbolAddress((void**)&pmid, g_mid);

    build_ell_kernel<<<N_NODES, 256>>>(adj);

    const float* Xprev = x;
    float* Xouts[3] = {pX1, pX2, out_h3};
    for (int L = 0; L < 3; L++) {
        wavec_kernel<<<1, 256>>>(W[L], a[L]);
        s12_kernel<<<N_NODES / 8, 256>>>(Xprev);
        gemm_kernel<0, 1><<<dim3(D / 64, N_NODES / 128), 256>>>(Xprev, W[L], nullptr, ph,
                                                                N_NODES, D, D);
        colsum_part_kernel<<<32, 256>>>();
        colsum_red_kernel<<<1, 256>>>();
        gat_row_kernel<<<N_NODES, 128>>>(Xprev, lng[L], lnb[L], Xouts[L], L > 0 ? 1 : 0);
        Xprev = Xouts[L];
    }

    // node head: mid = gelu(h3 @ nc_w1 + b1); logits = mid @ nc_w2 + b2
    gemm_kernel<1, 0><<<dim3(1, N_NODES / 128), 256>>>(out_h3, nc_w1, nc_b1, pmid,
                                                       N_NODES, 64, D);
    node_logits_kernel<<<N_NODES, 64>>>(pmid, nc_w2, nc_b2, out_node);

    // graph heads
    pool_part_kernel<<<64, 256>>>(out_h3, mask);
    pool_red_kernel<<<NG, 256>>>();
    graph_head_kernel<<<1, 256>>>(gc_w1, gc_b1, gc_w2, gc_b2,
                                  rs_w1, rs_b1, rs_w2, rs_b2,
                                  out_graph, out_risk);
}